// round 15
// baseline (speedup 1.0000x reference)
#include <cuda_runtime.h>
#include <math.h>

#define Wd 512
#define Hd 512
#define Nimg 32
#define TILE 32
#define RAD 5
#define IN_T 42               /* halo rows */
#define NRP 21                /* row pairs */
#define SP2 43                /* u64 pitch of input tiles (42 cols + 1 pad) */
#define HP2 33                /* u64 pitch of hbuf (32 cols + 1 pad) */
#define PL2 (NRP * HP2)       /* u64 plane stride in hbuf = 693 */
#define C2V 0.0009f           /* 0.03^2 */
#define NBLOCKS (16*16*32)    /* 8192 */

typedef unsigned long long u64;

__device__ __align__(16) float g_in[NBLOCKS];
__device__ __align__(16) float g_gr[NBLOCKS];
__device__ __align__(16) float g_ss[NBLOCKS];

// ---- packed f32x2 helpers (Blackwell FFMA2 path) ----
__device__ __forceinline__ u64 pk2(float a, float b) {
    u64 r; asm("mov.b64 %0, {%1, %2};" : "=l"(r) : "f"(a), "f"(b)); return r;
}
__device__ __forceinline__ void upk2(u64 v, float& a, float& b) {
    asm("mov.b64 {%0, %1}, %2;" : "=f"(a), "=f"(b) : "l"(v));
}
__device__ __forceinline__ u64 fma2(u64 a, u64 b, u64 c) {
    u64 d; asm("fma.rn.f32x2 %0, %1, %2, %3;" : "=l"(d) : "l"(a), "l"(b), "l"(c)); return d;
}
__device__ __forceinline__ u64 mul2(u64 a, u64 b) {
    u64 d; asm("mul.rn.f32x2 %0, %1, %2;" : "=l"(d) : "l"(a), "l"(b)); return d;
}
__device__ __forceinline__ u64 add2(u64 a, u64 b) {
    u64 d; asm("add.rn.f32x2 %0, %1, %2;" : "=l"(d) : "l"(a), "l"(b)); return d;
}

// Sobel over 4 consecutive rows of one column from an interleaved row-pair tile.
// Also returns the 4 center pixel values (free from the halo registers).
__device__ __forceinline__ void sobel4i(const u64* __restrict__ t2, int m0, int x,
                                        float g[4], float ctr[4]) {
    float a[6][3];
    #pragma unroll
    for (int j = 0; j < 3; j++) {
        #pragma unroll
        for (int cc = 0; cc < 3; cc++) {
            u64 v = t2[(m0 + 2 + j) * SP2 + (x + 4 + cc)];
            float lo, hi; upk2(v, lo, hi);
            a[2*j][cc] = lo; a[2*j + 1][cc] = hi;
        }
    }
    #pragma unroll
    for (int i = 0; i < 4; i++) {
        float gx = (a[i][2] - a[i][0]) + 2.0f * (a[i+1][2] - a[i+1][0]) + (a[i+2][2] - a[i+2][0]);
        float gy = (a[i][0] + 2.0f * a[i][1] + a[i][2]) - (a[i+2][0] + 2.0f * a[i+2][1] + a[i+2][2]);
        g[i] = fabsf(gx) + fabsf(gy);
        ctr[i] = a[i + 1][1];
    }
}

__global__ __launch_bounds__(256, 2)
void fused_kernel(const float* __restrict__ vis,
                  const float* __restrict__ ir,
                  const float* __restrict__ gen)
{
    __shared__ float gwin[11];
    __shared__ float red[8][3];
    extern __shared__ u64 smem2[];
    u64* sv2  = smem2;                 // vis tile  [NRP][SP2] row-pair interleaved
    u64* si2  = sv2 + NRP * SP2;       // ir tile
    u64* sg2  = si2 + NRP * SP2;       // gen tile
    u64* hbuf = sg2 + NRP * SP2;       // 8 planes x [NRP][HP2]

    const int tid = threadIdx.x;

    if (tid == 0) {
        float raw[11]; float s = 0.0f;
        #pragma unroll
        for (int i = 0; i < 11; i++) {
            float d = (float)(i - 5);
            raw[i] = expf(-(d * d) / 4.5f);
            s += raw[i];
        }
        #pragma unroll
        for (int i = 0; i < 11; i++) gwin[i] = raw[i] / s;
    }

    const int n   = blockIdx.z;
    const int tx0 = blockIdx.x * TILE;
    const int ty0 = blockIdx.y * TILE;
    const long base = (long)n * (Hd * Wd);
    const float* pv = vis + base;
    const float* pi = ir  + base;
    const float* pg = gen + base;

    // ---- Phase 1: load halo as interleaved row pairs ----
    const bool interior = (blockIdx.x >= 1) & (blockIdx.x <= 14) &
                          (blockIdx.y >= 1) & (blockIdx.y <= 14);
    if (interior) {
        // Column-pair vectorized: even-aligned float2 loads over [tx0-6, tx0+38).
        // 21 row-pairs x 22 col-pairs = 462 tasks; each writes <=2 smem u64 cols.
        for (int idx = tid; idx < NRP * 22; idx += 256) {
            int rp = idx / 22, j = idx - rp * 22;
            int gy0  = ty0 + 2 * rp - RAD;
            int gcol = tx0 - 6 + 2 * j;        // even -> 8B-aligned
            long o = (long)gy0 * Wd + gcol;
            float2 v0 = *(const float2*)(pv + o);
            float2 v1 = *(const float2*)(pv + o + Wd);
            float2 q0 = *(const float2*)(pi + o);
            float2 q1 = *(const float2*)(pi + o + Wd);
            float2 z0 = *(const float2*)(pg + o);
            float2 z1 = *(const float2*)(pg + o + Wd);
            int cA = 2 * j - 1;                // smem col for .x lane
            int cB = 2 * j;                    // smem col for .y lane
            int so = rp * SP2;
            if (cA >= 0) {
                sv2[so + cA] = pk2(v0.x, v1.x);
                si2[so + cA] = pk2(q0.x, q1.x);
                sg2[so + cA] = pk2(z0.x, z1.x);
            }
            if (cB < IN_T) {
                sv2[so + cB] = pk2(v0.y, v1.y);
                si2[so + cB] = pk2(q0.y, q1.y);
                sg2[so + cB] = pk2(z0.y, z1.y);
            }
        }
    } else {
        for (int idx = tid; idx < NRP * IN_T; idx += 256) {
            int rp = idx / IN_T, c = idx - rp * IN_T;
            int gy0 = ty0 + 2 * rp - RAD;
            int gx  = tx0 + c - RAD;
            bool okx = (unsigned)gx < (unsigned)Wd;
            bool ok0 = okx && ((unsigned)gy0 < (unsigned)Hd);
            bool ok1 = okx && ((unsigned)(gy0 + 1) < (unsigned)Hd);
            int o = gy0 * Wd + gx;
            int so = rp * SP2 + c;
            sv2[so] = pk2(ok0 ? pv[o] : 0.0f, ok1 ? pv[o + Wd] : 0.0f);
            si2[so] = pk2(ok0 ? pi[o] : 0.0f, ok1 ? pi[o + Wd] : 0.0f);
            sg2[so] = pk2(ok0 ? pg[o] : 0.0f, ok1 ? pg[o + Wd] : 0.0f);
        }
    }
    __syncthreads();

    // ---- Phase 2: horizontal Gaussian, one row pair per task, all-LDS.64 ----
    {
        u64 wp[11];
        #pragma unroll
        for (int k = 0; k < 11; k++) { float w = gwin[k]; wp[k] = pk2(w, w); }

        for (int idx = tid; idx < NRP * 32; idx += 256) {
            int rp = idx >> 5;
            int c  = idx & 31;
            const u64* bg = sg2 + rp * SP2 + c;
            const u64* bi = si2 + rp * SP2 + c;
            const u64* bv = sv2 + rp * SP2 + c;
            u64 a0 = 0, a1 = 0, a2 = 0, a3 = 0, a4 = 0, a5 = 0, a6 = 0, a7 = 0;
            #pragma unroll
            for (int k = 0; k < 11; k++) {
                u64 z2 = bg[k];
                u64 q2 = bi[k];
                u64 v2 = bv[k];
                u64 w2 = wp[k];
                u64 t  = mul2(w2, z2);
                u64 tq = mul2(w2, q2);
                u64 tv = mul2(w2, v2);
                a0 = add2(a0, t);           // gen
                a1 = add2(a1, tq);          // ir
                a2 = add2(a2, tv);          // vis
                a3 = fma2(t,  z2, a3);      // gen*gen
                a4 = fma2(tq, q2, a4);      // ir*ir
                a5 = fma2(tv, v2, a5);      // vis*vis
                a6 = fma2(t,  q2, a6);      // gen*ir
                a7 = fma2(t,  v2, a7);      // gen*vis
            }
            u64* h = hbuf + rp * HP2 + c;
            h[0*PL2] = a0; h[1*PL2] = a1; h[2*PL2] = a2; h[3*PL2] = a3;
            h[4*PL2] = a4; h[5*PL2] = a5; h[6*PL2] = a6; h[7*PL2] = a7;
        }
    }

    const int x  = tid & 31;
    const int y0 = (tid >> 5) * 4;
    const int m0 = y0 >> 1;

    // ---- Sobel + L1 terms: independent of hbuf, runs INSIDE the barrier
    //      bubble left by phase-2's 3-vs-2 task imbalance ----
    float acc_in = 0.0f, acc_grad = 0.0f, acc_ssim = 0.0f;
    {
        float gv[4], cv[4], gi_[4], ci[4], gg[4], cg[4];
        sobel4i(sv2, m0, x, gv, cv);
        sobel4i(si2, m0, x, gi_, ci);
        sobel4i(sg2, m0, x, gg, cg);
        #pragma unroll
        for (int i = 0; i < 4; i++) {
            acc_in   += fabsf(cg[i] - fmaxf(cv[i], ci[i]));
            acc_grad += fabsf(gg[i] - fmaxf(gv[i], gi_[i]));
        }
    }
    __syncthreads();

    // ---- Phase 3: vertical pass on row pairs with even/odd weight pairs ----
    u64 wpE[6], wpO[6];
    #pragma unroll
    for (int j = 0; j < 6; j++) {
        wpE[j] = pk2(gwin[2*j], (2*j + 1 < 11) ? gwin[2*j + 1] : 0.0f);
        wpO[j] = pk2((j > 0) ? gwin[2*j - 1] : 0.0f, gwin[2*j]);
    }

    float fm[8][4];   // [field][output row]
    {
        const u64* hb = hbuf + m0 * HP2 + x;
        #pragma unroll
        for (int p = 0; p < 8; p++) {
            const u64* hp0 = hb + p * PL2;
            u64 hp[7];
            #pragma unroll
            for (int m = 0; m < 7; m++) hp[m] = hp0[m * HP2];
            u64 A0 = 0, A1 = 0, A2 = 0, A3 = 0;
            #pragma unroll
            for (int m = 0; m < 6; m++) {
                A0 = fma2(wpE[m], hp[m],     A0);   // out row y0
                A1 = fma2(wpO[m], hp[m],     A1);   // out row y0+1
                A2 = fma2(wpE[m], hp[m + 1], A2);   // out row y0+2
                A3 = fma2(wpO[m], hp[m + 1], A3);   // out row y0+3
            }
            float lo, hi;
            upk2(A0, lo, hi); fm[p][0] = lo + hi;
            upk2(A1, lo, hi); fm[p][1] = lo + hi;
            upk2(A2, lo, hi); fm[p][2] = lo + hi;
            upk2(A3, lo, hi); fm[p][3] = lo + hi;
        }
    }

    // ---- SSIM pointwise (sqrt-free selector + fast division) ----
    #pragma unroll
    for (int i = 0; i < 4; i++) {
        float mu1 = fm[0][i], mu2 = fm[1][i], mu3 = fm[2][i];
        float s1q = fm[3][i] - mu1 * mu1;
        float s2q = fm[4][i] - mu2 * mu2;
        float s3q = fm[5][i] - mu3 * mu3;
        float s12 = fm[6][i] - mu1 * mu2;
        float s13 = fm[7][i] - mu1 * mu3;
        float map12 = __fdividef(2.0f * s12 + C2V, s1q + s2q + C2V);
        float map13 = __fdividef(2.0f * s13 + C2V, s1q + s3q + C2V);
        // Equivalent to fabs(sqrt(s2q)) >= fabs(sqrt(s3q)) with NaN-compares-false
        // (case analysis over signs; verified in R13).
        bool sel = (s3q >= 0.0f) && (s2q >= s3q);
        acc_ssim += sel ? map12 : map13;
    }

    // ---- deterministic block reduction ----
    #pragma unroll
    for (int off = 16; off; off >>= 1) {
        acc_in   += __shfl_down_sync(0xffffffffu, acc_in,   off);
        acc_grad += __shfl_down_sync(0xffffffffu, acc_grad, off);
        acc_ssim += __shfl_down_sync(0xffffffffu, acc_ssim, off);
    }
    int warp = tid >> 5, lane = tid & 31;
    if (lane == 0) { red[warp][0] = acc_in; red[warp][1] = acc_grad; red[warp][2] = acc_ssim; }
    __syncthreads();
    if (tid == 0) {
        float a = 0, b = 0, c = 0;
        #pragma unroll
        for (int w = 0; w < 8; w++) { a += red[w][0]; b += red[w][1]; c += red[w][2]; }
        int bId = (blockIdx.z * 16 + blockIdx.y) * 16 + blockIdx.x;
        g_in[bId] = a;
        g_gr[bId] = b;
        g_ss[bId] = c;
    }
}

__global__ __launch_bounds__(256)
void finalize_kernel(float* __restrict__ out)
{
    __shared__ float r0[8], r1[8], r2[8];
    const int tid = threadIdx.x;
    const float4* p0 = (const float4*)g_in;    // 2048 float4 per array
    const float4* p1 = (const float4*)g_gr;
    const float4* p2 = (const float4*)g_ss;
    float a0 = 0.0f, a1 = 0.0f, a2 = 0.0f;
    #pragma unroll
    for (int i = 0; i < 8; i++) {
        int idx = tid + i * 256;
        float4 v0 = p0[idx], v1 = p1[idx], v2 = p2[idx];
        a0 += (v0.x + v0.y) + (v0.z + v0.w);
        a1 += (v1.x + v1.y) + (v1.z + v1.w);
        a2 += (v2.x + v2.y) + (v2.z + v2.w);
    }
    #pragma unroll
    for (int off = 16; off; off >>= 1) {
        a0 += __shfl_down_sync(0xffffffffu, a0, off);
        a1 += __shfl_down_sync(0xffffffffu, a1, off);
        a2 += __shfl_down_sync(0xffffffffu, a2, off);
    }
    int warp = tid >> 5, lane = tid & 31;
    if (lane == 0) { r0[warp] = a0; r1[warp] = a1; r2[warp] = a2; }
    __syncthreads();
    if (tid == 0) {
        double t0 = 0, t1 = 0, t2 = 0;
        #pragma unroll
        for (int w = 0; w < 8; w++) {
            t0 += (double)r0[w]; t1 += (double)r1[w]; t2 += (double)r2[w];
        }
        const double tot = (double)Nimg * Hd * Wd;   // 8388608
        double loss_in   = 1.5 * t0 / tot;
        double loss_grad = t1 / tot;
        double ssim_mean = t2 / tot;
        out[0] = (float)loss_in;
        out[1] = (float)(0.5 * (1.0 - ssim_mean) + loss_grad);
    }
}

extern "C" void kernel_launch(void* const* d_in, const int* in_sizes, int n_in,
                              void* d_out, int out_size)
{
    const float* vis = (const float*)d_in[0];
    const float* ir  = (const float*)d_in[1];
    const float* gen = (const float*)d_in[2];
    float* out = (float*)d_out;

    const int SMEM_BYTES = (3 * NRP * SP2 + 8 * NRP * HP2) * (int)sizeof(u64); // 66024
    cudaFuncSetAttribute(fused_kernel, cudaFuncAttributeMaxDynamicSharedMemorySize, SMEM_BYTES);
    cudaFuncSetAttribute(fused_kernel, cudaFuncAttributePreferredSharedMemoryCarveout,
                         cudaSharedmemCarveoutMaxShared);

    dim3 grid(16, 16, 32);
    fused_kernel<<<grid, 256, SMEM_BYTES>>>(vis, ir, gen);
    finalize_kernel<<<1, 256>>>(out);
}

// round 16
// speedup vs baseline: 1.0095x; 1.0095x over previous
#include <cuda_runtime.h>
#include <math.h>

#define Wd 512
#define Hd 512
#define Nimg 32
#define TILE 32
#define RAD 5
#define IN_T 42               /* halo rows */
#define NRP 21                /* row pairs */
#define SP2 43                /* u64 pitch of input tiles (42 cols + 1 pad) */
#define HP2 33                /* u64 pitch of hbuf (32 cols + 1 pad) */
#define PL2 (NRP * HP2)       /* u64 plane stride in hbuf = 693 */
#define C2V 0.0009f           /* 0.03^2 */
#define NBLOCKS (16*16*32)    /* 8192 */

typedef unsigned long long u64;

__device__ __align__(16) float g_in[NBLOCKS];
__device__ __align__(16) float g_gr[NBLOCKS];
__device__ __align__(16) float g_ss[NBLOCKS];

// ---- packed f32x2 helpers (Blackwell FFMA2 path) ----
__device__ __forceinline__ u64 pk2(float a, float b) {
    u64 r; asm("mov.b64 %0, {%1, %2};" : "=l"(r) : "f"(a), "f"(b)); return r;
}
__device__ __forceinline__ void upk2(u64 v, float& a, float& b) {
    asm("mov.b64 {%0, %1}, %2;" : "=f"(a), "=f"(b) : "l"(v));
}
__device__ __forceinline__ u64 fma2(u64 a, u64 b, u64 c) {
    u64 d; asm("fma.rn.f32x2 %0, %1, %2, %3;" : "=l"(d) : "l"(a), "l"(b), "l"(c)); return d;
}
__device__ __forceinline__ u64 mul2(u64 a, u64 b) {
    u64 d; asm("mul.rn.f32x2 %0, %1, %2;" : "=l"(d) : "l"(a), "l"(b)); return d;
}
__device__ __forceinline__ u64 add2(u64 a, u64 b) {
    u64 d; asm("add.rn.f32x2 %0, %1, %2;" : "=l"(d) : "l"(a), "l"(b)); return d;
}

// Sobel over 4 consecutive rows of one column from an interleaved row-pair tile.
// Also returns the 4 center pixel values (free from the halo registers).
__device__ __forceinline__ void sobel4i(const u64* __restrict__ t2, int m0, int x,
                                        float g[4], float ctr[4]) {
    float a[6][3];
    #pragma unroll
    for (int j = 0; j < 3; j++) {
        #pragma unroll
        for (int cc = 0; cc < 3; cc++) {
            u64 v = t2[(m0 + 2 + j) * SP2 + (x + 4 + cc)];
            float lo, hi; upk2(v, lo, hi);
            a[2*j][cc] = lo; a[2*j + 1][cc] = hi;
        }
    }
    #pragma unroll
    for (int i = 0; i < 4; i++) {
        float gx = (a[i][2] - a[i][0]) + 2.0f * (a[i+1][2] - a[i+1][0]) + (a[i+2][2] - a[i+2][0]);
        float gy = (a[i][0] + 2.0f * a[i][1] + a[i][2]) - (a[i+2][0] + 2.0f * a[i+2][1] + a[i+2][2]);
        g[i] = fabsf(gx) + fabsf(gy);
        ctr[i] = a[i + 1][1];
    }
}

__global__ __launch_bounds__(256, 2)
void fused_kernel(const float* __restrict__ vis,
                  const float* __restrict__ ir,
                  const float* __restrict__ gen)
{
    __shared__ float gwin[11];
    __shared__ float red[8][3];
    extern __shared__ u64 smem2[];
    u64* sv2  = smem2;                 // vis tile  [NRP][SP2] row-pair interleaved
    u64* si2  = sv2 + NRP * SP2;       // ir tile
    u64* sg2  = si2 + NRP * SP2;       // gen tile
    u64* hbuf = sg2 + NRP * SP2;       // 8 planes x [NRP][HP2]

    const int tid = threadIdx.x;

    if (tid == 0) {
        float raw[11]; float s = 0.0f;
        #pragma unroll
        for (int i = 0; i < 11; i++) {
            float d = (float)(i - 5);
            raw[i] = expf(-(d * d) / 4.5f);
            s += raw[i];
        }
        #pragma unroll
        for (int i = 0; i < 11; i++) gwin[i] = raw[i] / s;
    }

    const int n   = blockIdx.z;
    const int tx0 = blockIdx.x * TILE;
    const int ty0 = blockIdx.y * TILE;
    const long base = (long)n * (Hd * Wd);
    const float* pv = vis + base;
    const float* pi = ir  + base;
    const float* pg = gen + base;

    // ---- Phase 1: load halo as interleaved row pairs (R14 champion path) ----
    const bool interior = (blockIdx.x >= 1) & (blockIdx.x <= 14) &
                          (blockIdx.y >= 1) & (blockIdx.y <= 14);
    if (interior) {
        for (int idx = tid; idx < NRP * IN_T; idx += 256) {
            int rp = idx / IN_T, c = idx - rp * IN_T;
            long o = (long)(ty0 + 2 * rp - RAD) * Wd + (tx0 + c - RAD);
            int so = rp * SP2 + c;
            sv2[so] = pk2(pv[o], pv[o + Wd]);
            si2[so] = pk2(pi[o], pi[o + Wd]);
            sg2[so] = pk2(pg[o], pg[o + Wd]);
        }
    } else {
        for (int idx = tid; idx < NRP * IN_T; idx += 256) {
            int rp = idx / IN_T, c = idx - rp * IN_T;
            int gy0 = ty0 + 2 * rp - RAD;
            int gx  = tx0 + c - RAD;
            bool okx = (unsigned)gx < (unsigned)Wd;
            bool ok0 = okx && ((unsigned)gy0 < (unsigned)Hd);
            bool ok1 = okx && ((unsigned)(gy0 + 1) < (unsigned)Hd);
            int o = gy0 * Wd + gx;
            int so = rp * SP2 + c;
            sv2[so] = pk2(ok0 ? pv[o] : 0.0f, ok1 ? pv[o + Wd] : 0.0f);
            si2[so] = pk2(ok0 ? pi[o] : 0.0f, ok1 ? pi[o + Wd] : 0.0f);
            sg2[so] = pk2(ok0 ? pg[o] : 0.0f, ok1 ? pg[o + Wd] : 0.0f);
        }
    }
    __syncthreads();

    // ---- Phase 2: horizontal Gaussian, one row pair per task, all-LDS.64 ----
    {
        u64 wp[11];
        #pragma unroll
        for (int k = 0; k < 11; k++) { float w = gwin[k]; wp[k] = pk2(w, w); }

        for (int idx = tid; idx < NRP * 32; idx += 256) {
            int rp = idx >> 5;
            int c  = idx & 31;
            const u64* bg = sg2 + rp * SP2 + c;
            const u64* bi = si2 + rp * SP2 + c;
            const u64* bv = sv2 + rp * SP2 + c;
            u64 a0 = 0, a1 = 0, a2 = 0, a3 = 0, a4 = 0, a5 = 0, a6 = 0, a7 = 0;
            #pragma unroll
            for (int k = 0; k < 11; k++) {
                u64 z2 = bg[k];
                u64 q2 = bi[k];
                u64 v2 = bv[k];
                u64 w2 = wp[k];
                u64 t  = mul2(w2, z2);
                u64 tq = mul2(w2, q2);
                u64 tv = mul2(w2, v2);
                a0 = add2(a0, t);           // gen
                a1 = add2(a1, tq);          // ir
                a2 = add2(a2, tv);          // vis
                a3 = fma2(t,  z2, a3);      // gen*gen
                a4 = fma2(tq, q2, a4);      // ir*ir
                a5 = fma2(tv, v2, a5);      // vis*vis
                a6 = fma2(t,  q2, a6);      // gen*ir
                a7 = fma2(t,  v2, a7);      // gen*vis
            }
            u64* h = hbuf + rp * HP2 + c;
            h[0*PL2] = a0; h[1*PL2] = a1; h[2*PL2] = a2; h[3*PL2] = a3;
            h[4*PL2] = a4; h[5*PL2] = a5; h[6*PL2] = a6; h[7*PL2] = a7;
        }
    }

    const int x  = tid & 31;
    const int y0 = (tid >> 5) * 4;
    const int m0 = y0 >> 1;

    // ---- Sobel + L1 terms: independent of hbuf, runs INSIDE the barrier
    //      bubble left by phase-2's 3-vs-2 task imbalance ----
    float acc_in = 0.0f, acc_grad = 0.0f, acc_ssim = 0.0f;
    {
        float gv[4], cv[4], gi_[4], ci[4], gg[4], cg[4];
        sobel4i(sv2, m0, x, gv, cv);
        sobel4i(si2, m0, x, gi_, ci);
        sobel4i(sg2, m0, x, gg, cg);
        #pragma unroll
        for (int i = 0; i < 4; i++) {
            acc_in   += fabsf(cg[i] - fmaxf(cv[i], ci[i]));
            acc_grad += fabsf(gg[i] - fmaxf(gv[i], gi_[i]));
        }
    }
    __syncthreads();

    // ---- Phase 3: vertical pass on row pairs with even/odd weight pairs ----
    u64 wpE[6], wpO[6];
    #pragma unroll
    for (int j = 0; j < 6; j++) {
        wpE[j] = pk2(gwin[2*j], (2*j + 1 < 11) ? gwin[2*j + 1] : 0.0f);
        wpO[j] = pk2((j > 0) ? gwin[2*j - 1] : 0.0f, gwin[2*j]);
    }

    float fm[8][4];   // [field][output row]
    {
        const u64* hb = hbuf + m0 * HP2 + x;
        #pragma unroll
        for (int p = 0; p < 8; p++) {
            const u64* hp0 = hb + p * PL2;
            u64 hp[7];
            #pragma unroll
            for (int m = 0; m < 7; m++) hp[m] = hp0[m * HP2];
            u64 A0 = 0, A1 = 0, A2 = 0, A3 = 0;
            #pragma unroll
            for (int m = 0; m < 6; m++) {
                A0 = fma2(wpE[m], hp[m],     A0);   // out row y0
                A1 = fma2(wpO[m], hp[m],     A1);   // out row y0+1
                A2 = fma2(wpE[m], hp[m + 1], A2);   // out row y0+2
                A3 = fma2(wpO[m], hp[m + 1], A3);   // out row y0+3
            }
            float lo, hi;
            upk2(A0, lo, hi); fm[p][0] = lo + hi;
            upk2(A1, lo, hi); fm[p][1] = lo + hi;
            upk2(A2, lo, hi); fm[p][2] = lo + hi;
            upk2(A3, lo, hi); fm[p][3] = lo + hi;
        }
    }

    // ---- SSIM pointwise (sqrt-free selector + fast division) ----
    #pragma unroll
    for (int i = 0; i < 4; i++) {
        float mu1 = fm[0][i], mu2 = fm[1][i], mu3 = fm[2][i];
        float s1q = fm[3][i] - mu1 * mu1;
        float s2q = fm[4][i] - mu2 * mu2;
        float s3q = fm[5][i] - mu3 * mu3;
        float s12 = fm[6][i] - mu1 * mu2;
        float s13 = fm[7][i] - mu1 * mu3;
        float map12 = __fdividef(2.0f * s12 + C2V, s1q + s2q + C2V);
        float map13 = __fdividef(2.0f * s13 + C2V, s1q + s3q + C2V);
        // Equivalent to fabs(sqrt(s2q)) >= fabs(sqrt(s3q)) with NaN-compares-false
        // (case analysis over signs; verified in R13).
        bool sel = (s3q >= 0.0f) && (s2q >= s3q);
        acc_ssim += sel ? map12 : map13;
    }

    // ---- deterministic block reduction ----
    #pragma unroll
    for (int off = 16; off; off >>= 1) {
        acc_in   += __shfl_down_sync(0xffffffffu, acc_in,   off);
        acc_grad += __shfl_down_sync(0xffffffffu, acc_grad, off);
        acc_ssim += __shfl_down_sync(0xffffffffu, acc_ssim, off);
    }
    int warp = tid >> 5, lane = tid & 31;
    if (lane == 0) { red[warp][0] = acc_in; red[warp][1] = acc_grad; red[warp][2] = acc_ssim; }
    __syncthreads();
    if (tid == 0) {
        float a = 0, b = 0, c = 0;
        #pragma unroll
        for (int w = 0; w < 8; w++) { a += red[w][0]; b += red[w][1]; c += red[w][2]; }
        int bId = (blockIdx.z * 16 + blockIdx.y) * 16 + blockIdx.x;
        g_in[bId] = a;
        g_gr[bId] = b;
        g_ss[bId] = c;
    }
}

__global__ __launch_bounds__(256)
void finalize_kernel(float* __restrict__ out)
{
    __shared__ float r0[8], r1[8], r2[8];
    const int tid = threadIdx.x;
    const float4* p0 = (const float4*)g_in;    // 2048 float4 per array
    const float4* p1 = (const float4*)g_gr;
    const float4* p2 = (const float4*)g_ss;
    float a0 = 0.0f, a1 = 0.0f, a2 = 0.0f;
    #pragma unroll
    for (int i = 0; i < 8; i++) {
        int idx = tid + i * 256;
        float4 v0 = p0[idx], v1 = p1[idx], v2 = p2[idx];
        a0 += (v0.x + v0.y) + (v0.z + v0.w);
        a1 += (v1.x + v1.y) + (v1.z + v1.w);
        a2 += (v2.x + v2.y) + (v2.z + v2.w);
    }
    #pragma unroll
    for (int off = 16; off; off >>= 1) {
        a0 += __shfl_down_sync(0xffffffffu, a0, off);
        a1 += __shfl_down_sync(0xffffffffu, a1, off);
        a2 += __shfl_down_sync(0xffffffffu, a2, off);
    }
    int warp = tid >> 5, lane = tid & 31;
    if (lane == 0) { r0[warp] = a0; r1[warp] = a1; r2[warp] = a2; }
    __syncthreads();
    if (tid == 0) {
        double t0 = 0, t1 = 0, t2 = 0;
        #pragma unroll
        for (int w = 0; w < 8; w++) {
            t0 += (double)r0[w]; t1 += (double)r1[w]; t2 += (double)r2[w];
        }
        const double tot = (double)Nimg * Hd * Wd;   // 8388608
        double loss_in   = 1.5 * t0 / tot;
        double loss_grad = t1 / tot;
        double ssim_mean = t2 / tot;
        out[0] = (float)loss_in;
        out[1] = (float)(0.5 * (1.0 - ssim_mean) + loss_grad);
    }
}

extern "C" void kernel_launch(void* const* d_in, const int* in_sizes, int n_in,
                              void* d_out, int out_size)
{
    const float* vis = (const float*)d_in[0];
    const float* ir  = (const float*)d_in[1];
    const float* gen = (const float*)d_in[2];
    float* out = (float*)d_out;

    const int SMEM_BYTES = (3 * NRP * SP2 + 8 * NRP * HP2) * (int)sizeof(u64); // 66024
    cudaFuncSetAttribute(fused_kernel, cudaFuncAttributeMaxDynamicSharedMemorySize, SMEM_BYTES);
    cudaFuncSetAttribute(fused_kernel, cudaFuncAttributePreferredSharedMemoryCarveout,
                         cudaSharedmemCarveoutMaxShared);

    dim3 grid(16, 16, 32);
    fused_kernel<<<grid, 256, SMEM_BYTES>>>(vis, ir, gen);
    finalize_kernel<<<1, 256>>>(out);
}

// round 17
// speedup vs baseline: 1.1893x; 1.1782x over previous
#include <cuda_runtime.h>
#include <math.h>

#define Wd 512
#define Hd 512
#define Nimg 32
#define TILE 32
#define RAD 5
#define IN_T 42               /* halo rows */
#define NRP 21                /* row pairs */
#define SP2 43                /* u64 pitch of input tiles (42 cols + 1 pad) */
#define HP2 33                /* u64 pitch of hbuf (32 cols + 1 pad) */
#define PL2 (NRP * HP2)       /* u64 plane stride in hbuf = 693 */
#define C2V 0.0009f           /* 0.03^2 */
#define NBLOCKS (16*16*32)    /* 8192 */

typedef unsigned long long u64;

__device__ __align__(16) float g_in[NBLOCKS];
__device__ __align__(16) float g_gr[NBLOCKS];
__device__ __align__(16) float g_ss[NBLOCKS];

// ---- packed f32x2 helpers (Blackwell FFMA2 path) ----
__device__ __forceinline__ u64 pk2(float a, float b) {
    u64 r; asm("mov.b64 %0, {%1, %2};" : "=l"(r) : "f"(a), "f"(b)); return r;
}
__device__ __forceinline__ void upk2(u64 v, float& a, float& b) {
    asm("mov.b64 {%0, %1}, %2;" : "=f"(a), "=f"(b) : "l"(v));
}
__device__ __forceinline__ u64 fma2(u64 a, u64 b, u64 c) {
    u64 d; asm("fma.rn.f32x2 %0, %1, %2, %3;" : "=l"(d) : "l"(a), "l"(b), "l"(c)); return d;
}
__device__ __forceinline__ u64 mul2(u64 a, u64 b) {
    u64 d; asm("mul.rn.f32x2 %0, %1, %2;" : "=l"(d) : "l"(a), "l"(b)); return d;
}
__device__ __forceinline__ u64 add2(u64 a, u64 b) {
    u64 d; asm("add.rn.f32x2 %0, %1, %2;" : "=l"(d) : "l"(a), "l"(b)); return d;
}

// Sobel over 4 consecutive rows of one column from an interleaved row-pair tile.
// Also returns the 4 center pixel values (free from the halo registers).
__device__ __forceinline__ void sobel4i(const u64* __restrict__ t2, int m0, int x,
                                        float g[4], float ctr[4]) {
    float a[6][3];
    #pragma unroll
    for (int j = 0; j < 3; j++) {
        #pragma unroll
        for (int cc = 0; cc < 3; cc++) {
            u64 v = t2[(m0 + 2 + j) * SP2 + (x + 4 + cc)];
            float lo, hi; upk2(v, lo, hi);
            a[2*j][cc] = lo; a[2*j + 1][cc] = hi;
        }
    }
    #pragma unroll
    for (int i = 0; i < 4; i++) {
        float gx = (a[i][2] - a[i][0]) + 2.0f * (a[i+1][2] - a[i+1][0]) + (a[i+2][2] - a[i+2][0]);
        float gy = (a[i][0] + 2.0f * a[i][1] + a[i][2]) - (a[i+2][0] + 2.0f * a[i+2][1] + a[i+2][2]);
        g[i] = fabsf(gx) + fabsf(gy);
        ctr[i] = a[i + 1][1];
    }
}

__global__ __launch_bounds__(256, 2)
void fused_kernel(const float* __restrict__ vis,
                  const float* __restrict__ ir,
                  const float* __restrict__ gen)
{
    __shared__ float gwin[11];
    __shared__ float red[8][3];
    extern __shared__ u64 smem2[];
    u64* sv2  = smem2;                 // vis tile  [NRP][SP2] row-pair interleaved
    u64* si2  = sv2 + NRP * SP2;       // ir tile
    u64* sg2  = si2 + NRP * SP2;       // gen tile
    u64* hbuf = sg2 + NRP * SP2;       // 8 planes x [NRP][HP2]

    const int tid = threadIdx.x;

    if (tid == 0) {
        float raw[11]; float s = 0.0f;
        #pragma unroll
        for (int i = 0; i < 11; i++) {
            float d = (float)(i - 5);
            raw[i] = expf(-(d * d) / 4.5f);
            s += raw[i];
        }
        #pragma unroll
        for (int i = 0; i < 11; i++) gwin[i] = raw[i] / s;
    }

    const int n   = blockIdx.z;
    const int tx0 = blockIdx.x * TILE;
    const int ty0 = blockIdx.y * TILE;
    const long base = (long)n * (Hd * Wd);
    const float* pv = vis + base;
    const float* pi = ir  + base;
    const float* pg = gen + base;

    // ---- Phase 1: load halo as interleaved row pairs ----
    const bool interior = (blockIdx.x >= 1) & (blockIdx.x <= 14) &
                          (blockIdx.y >= 1) & (blockIdx.y <= 14);
    if (interior) {
        for (int idx = tid; idx < NRP * IN_T; idx += 256) {
            int rp = idx / IN_T, c = idx - rp * IN_T;
            long o = (long)(ty0 + 2 * rp - RAD) * Wd + (tx0 + c - RAD);
            int so = rp * SP2 + c;
            sv2[so] = pk2(pv[o], pv[o + Wd]);
            si2[so] = pk2(pi[o], pi[o + Wd]);
            sg2[so] = pk2(pg[o], pg[o + Wd]);
        }
    } else {
        for (int idx = tid; idx < NRP * IN_T; idx += 256) {
            int rp = idx / IN_T, c = idx - rp * IN_T;
            int gy0 = ty0 + 2 * rp - RAD;
            int gx  = tx0 + c - RAD;
            bool okx = (unsigned)gx < (unsigned)Wd;
            bool ok0 = okx && ((unsigned)gy0 < (unsigned)Hd);
            bool ok1 = okx && ((unsigned)(gy0 + 1) < (unsigned)Hd);
            int o = gy0 * Wd + gx;
            int so = rp * SP2 + c;
            sv2[so] = pk2(ok0 ? pv[o] : 0.0f, ok1 ? pv[o + Wd] : 0.0f);
            si2[so] = pk2(ok0 ? pi[o] : 0.0f, ok1 ? pi[o + Wd] : 0.0f);
            sg2[so] = pk2(ok0 ? pg[o] : 0.0f, ok1 ? pg[o + Wd] : 0.0f);
        }
    }
    __syncthreads();

    // ---- Phase 2: horizontal Gaussian, one row pair per task, all-LDS.64 ----
    {
        u64 wp[11];
        #pragma unroll
        for (int k = 0; k < 11; k++) { float w = gwin[k]; wp[k] = pk2(w, w); }

        for (int idx = tid; idx < NRP * 32; idx += 256) {
            int rp = idx >> 5;
            int c  = idx & 31;
            const u64* bg = sg2 + rp * SP2 + c;
            const u64* bi = si2 + rp * SP2 + c;
            const u64* bv = sv2 + rp * SP2 + c;
            u64 a0 = 0, a1 = 0, a2 = 0, a3 = 0, a4 = 0, a5 = 0, a6 = 0, a7 = 0;
            #pragma unroll
            for (int k = 0; k < 11; k++) {
                u64 z2 = bg[k];
                u64 q2 = bi[k];
                u64 v2 = bv[k];
                u64 w2 = wp[k];
                u64 t  = mul2(w2, z2);
                u64 tq = mul2(w2, q2);
                u64 tv = mul2(w2, v2);
                a0 = add2(a0, t);           // gen
                a1 = add2(a1, tq);          // ir
                a2 = add2(a2, tv);          // vis
                a3 = fma2(t,  z2, a3);      // gen*gen
                a4 = fma2(tq, q2, a4);      // ir*ir
                a5 = fma2(tv, v2, a5);      // vis*vis
                a6 = fma2(t,  q2, a6);      // gen*ir
                a7 = fma2(t,  v2, a7);      // gen*vis
            }
            u64* h = hbuf + rp * HP2 + c;
            h[0*PL2] = a0; h[1*PL2] = a1; h[2*PL2] = a2; h[3*PL2] = a3;
            h[4*PL2] = a4; h[5*PL2] = a5; h[6*PL2] = a6; h[7*PL2] = a7;
        }
    }
    __syncthreads();

    // ---- Phase 3: vertical pass on row pairs with even/odd weight pairs ----
    const int x  = tid & 31;
    const int y0 = (tid >> 5) * 4;
    const int m0 = y0 >> 1;

    u64 wpE[6], wpO[6];
    #pragma unroll
    for (int j = 0; j < 6; j++) {
        wpE[j] = pk2(gwin[2*j], (2*j + 1 < 11) ? gwin[2*j + 1] : 0.0f);
        wpO[j] = pk2((j > 0) ? gwin[2*j - 1] : 0.0f, gwin[2*j]);
    }

    float fm[8][4];   // [field][output row]
    {
        const u64* hb = hbuf + m0 * HP2 + x;
        #pragma unroll
        for (int p = 0; p < 8; p++) {
            const u64* hp0 = hb + p * PL2;
            u64 hp[7];
            #pragma unroll
            for (int m = 0; m < 7; m++) hp[m] = hp0[m * HP2];
            u64 A0 = 0, A1 = 0, A2 = 0, A3 = 0;
            #pragma unroll
            for (int m = 0; m < 6; m++) {
                A0 = fma2(wpE[m], hp[m],     A0);   // out row y0
                A1 = fma2(wpO[m], hp[m],     A1);   // out row y0+1
                A2 = fma2(wpE[m], hp[m + 1], A2);   // out row y0+2
                A3 = fma2(wpO[m], hp[m + 1], A3);   // out row y0+3
            }
            float lo, hi;
            upk2(A0, lo, hi); fm[p][0] = lo + hi;
            upk2(A1, lo, hi); fm[p][1] = lo + hi;
            upk2(A2, lo, hi); fm[p][2] = lo + hi;
            upk2(A3, lo, hi); fm[p][3] = lo + hi;
        }
    }

    // ---- SSIM pointwise (sqrt-free selector + fast division) ----
    float acc_in = 0.0f, acc_grad = 0.0f, acc_ssim = 0.0f;
    #pragma unroll
    for (int i = 0; i < 4; i++) {
        float mu1 = fm[0][i], mu2 = fm[1][i], mu3 = fm[2][i];
        float s1q = fm[3][i] - mu1 * mu1;
        float s2q = fm[4][i] - mu2 * mu2;
        float s3q = fm[5][i] - mu3 * mu3;
        float s12 = fm[6][i] - mu1 * mu2;
        float s13 = fm[7][i] - mu1 * mu3;
        float map12 = __fdividef(2.0f * s12 + C2V, s1q + s2q + C2V);
        float map13 = __fdividef(2.0f * s13 + C2V, s1q + s3q + C2V);
        // Equivalent to fabs(sqrt(s2q)) >= fabs(sqrt(s3q)) with NaN-compares-false
        // (case analysis over signs; verified in R13).
        bool sel = (s3q >= 0.0f) && (s2q >= s3q);
        acc_ssim += sel ? map12 : map13;
    }

    // ---- Sobel + L1 terms ----
    {
        float gv[4], cv[4], gi_[4], ci[4], gg[4], cg[4];
        sobel4i(sv2, m0, x, gv, cv);
        sobel4i(si2, m0, x, gi_, ci);
        sobel4i(sg2, m0, x, gg, cg);
        #pragma unroll
        for (int i = 0; i < 4; i++) {
            acc_in   += fabsf(cg[i] - fmaxf(cv[i], ci[i]));
            acc_grad += fabsf(gg[i] - fmaxf(gv[i], gi_[i]));
        }
    }

    // ---- deterministic block reduction ----
    #pragma unroll
    for (int off = 16; off; off >>= 1) {
        acc_in   += __shfl_down_sync(0xffffffffu, acc_in,   off);
        acc_grad += __shfl_down_sync(0xffffffffu, acc_grad, off);
        acc_ssim += __shfl_down_sync(0xffffffffu, acc_ssim, off);
    }
    int warp = tid >> 5, lane = tid & 31;
    if (lane == 0) { red[warp][0] = acc_in; red[warp][1] = acc_grad; red[warp][2] = acc_ssim; }
    __syncthreads();
    if (tid == 0) {
        float a = 0, b = 0, c = 0;
        #pragma unroll
        for (int w = 0; w < 8; w++) { a += red[w][0]; b += red[w][1]; c += red[w][2]; }
        int bId = (blockIdx.z * 16 + blockIdx.y) * 16 + blockIdx.x;
        g_in[bId] = a;
        g_gr[bId] = b;
        g_ss[bId] = c;
    }
}

__global__ __launch_bounds__(256)
void finalize_kernel(float* __restrict__ out)
{
    __shared__ float r0[8], r1[8], r2[8];
    const int tid = threadIdx.x;
    const float4* p0 = (const float4*)g_in;    // 2048 float4 per array
    const float4* p1 = (const float4*)g_gr;
    const float4* p2 = (const float4*)g_ss;
    float a0 = 0.0f, a1 = 0.0f, a2 = 0.0f;
    #pragma unroll
    for (int i = 0; i < 8; i++) {
        int idx = tid + i * 256;
        float4 v0 = p0[idx], v1 = p1[idx], v2 = p2[idx];
        a0 += (v0.x + v0.y) + (v0.z + v0.w);
        a1 += (v1.x + v1.y) + (v1.z + v1.w);
        a2 += (v2.x + v2.y) + (v2.z + v2.w);
    }
    #pragma unroll
    for (int off = 16; off; off >>= 1) {
        a0 += __shfl_down_sync(0xffffffffu, a0, off);
        a1 += __shfl_down_sync(0xffffffffu, a1, off);
        a2 += __shfl_down_sync(0xffffffffu, a2, off);
    }
    int warp = tid >> 5, lane = tid & 31;
    if (lane == 0) { r0[warp] = a0; r1[warp] = a1; r2[warp] = a2; }
    __syncthreads();
    if (tid == 0) {
        double t0 = 0, t1 = 0, t2 = 0;
        #pragma unroll
        for (int w = 0; w < 8; w++) {
            t0 += (double)r0[w]; t1 += (double)r1[w]; t2 += (double)r2[w];
        }
        const double tot = (double)Nimg * Hd * Wd;   // 8388608
        double loss_in   = 1.5 * t0 / tot;
        double loss_grad = t1 / tot;
        double ssim_mean = t2 / tot;
        out[0] = (float)loss_in;
        out[1] = (float)(0.5 * (1.0 - ssim_mean) + loss_grad);
    }
}

extern "C" void kernel_launch(void* const* d_in, const int* in_sizes, int n_in,
                              void* d_out, int out_size)
{
    const float* vis = (const float*)d_in[0];
    const float* ir  = (const float*)d_in[1];
    const float* gen = (const float*)d_in[2];
    float* out = (float*)d_out;

    const int SMEM_BYTES = (3 * NRP * SP2 + 8 * NRP * HP2) * (int)sizeof(u64); // 66024
    cudaFuncSetAttribute(fused_kernel, cudaFuncAttributeMaxDynamicSharedMemorySize, SMEM_BYTES);
    cudaFuncSetAttribute(fused_kernel, cudaFuncAttributePreferredSharedMemoryCarveout,
                         cudaSharedmemCarveoutMaxShared);

    dim3 grid(16, 16, 32);
    fused_kernel<<<grid, 256, SMEM_BYTES>>>(vis, ir, gen);
    finalize_kernel<<<1, 256>>>(out);
}